// round 14
// baseline (speedup 1.0000x reference)
#include <cuda_runtime.h>
#include <cuda_bf16.h>
#include <cuda_fp16.h>
#include <cstdint>

#define NN 50000
#define EE 600000
#define HH 128
#define LL 4
#define GG 256
#define CC 10
#define BN_EPS 1e-5f

#define SCAN_BLOCKS ((NN + 255) / 256)   // 196
#define STAT_SLICES 4                    // spread stat atomics 4-way

// -------- device scratch (no allocations allowed) --------
__device__ __half d_hl[LL][NN * HH]; // pre-BN z2 per layer (fp16)
__device__ float d_z[NN * HH];       // agg output (fp32)
__device__ float d_y[NN * HH];       // GEMM1 output (fp32)
__device__ float d_pool[GG * LL * HH];
// raw per-layer stats, 4 slices of [sum(128), sumsq(128)]
__device__ float d_stA[LL][STAT_SLICES * 2 * HH];
__device__ float d_stB[LL][STAT_SLICES * 2 * HH];
__device__ int   d_start[GG + 1];
// CSR (dst-sorted adjacency)
__device__ int   d_cnt[NN];
__device__ int   d_cur[NN];
__device__ int   d_rowptr[NN + 1];
__device__ int   d_col[EE];
__device__ int   d_bsum[256];
__device__ int   d_boff[256];

// -------- init: graph bounds + zero counters + zero stats --------
__global__ void k_init(const int* __restrict__ batch) {
    int n = blockIdx.x * blockDim.x + threadIdx.x;
    if (n < NN) {
        d_cnt[n] = 0;
        d_cur[n] = 0;
        int g = batch[n];
        if (n == 0) {
            for (int gg = 0; gg <= g; ++gg) d_start[gg] = 0;
        } else {
            int gp = batch[n - 1];
            for (int gg = gp + 1; gg <= g; ++gg) d_start[gg] = n;
        }
        if (n == NN - 1) {
            for (int gg = g + 1; gg <= GG; ++gg) d_start[gg] = NN;
        }
    }
    if (n < LL * STAT_SLICES * 2 * HH) {
        ((float*)d_stA)[n] = 0.f;
        ((float*)d_stB)[n] = 0.f;
    }
}

__global__ void k_hist(const int* __restrict__ dst) {
    int i = blockIdx.x * blockDim.x + threadIdx.x;
    if (i >= EE / 4) return;
    int4 d = ((const int4*)dst)[i];
    atomicAdd(&d_cnt[d.x], 1);
    atomicAdd(&d_cnt[d.y], 1);
    atomicAdd(&d_cnt[d.z], 1);
    atomicAdd(&d_cnt[d.w], 1);
}

__global__ void k_scan1() {
    __shared__ int sp[256];
    int t = threadIdx.x;
    int i = blockIdx.x * 256 + t;
    int v = (i < NN) ? d_cnt[i] : 0;
    sp[t] = v;
    __syncthreads();
    for (int off = 128; off > 0; off >>= 1) {
        if (t < off) sp[t] += sp[t + off];
        __syncthreads();
    }
    if (t == 0) d_bsum[blockIdx.x] = sp[0];
}

__global__ void k_scan2() {
    __shared__ int sp[256];
    int t = threadIdx.x;
    int v = (t < SCAN_BLOCKS) ? d_bsum[t] : 0;
    sp[t] = v;
    __syncthreads();
    for (int off = 1; off < 256; off <<= 1) {
        int u = 0;
        if (t >= off) u = sp[t - off];
        __syncthreads();
        if (t >= off) sp[t] += u;
        __syncthreads();
    }
    d_boff[t] = sp[t] - v;
    if (t == 0) d_rowptr[NN] = EE;
}

__global__ void k_scan3() {
    __shared__ int sp[256];
    int t = threadIdx.x;
    int i = blockIdx.x * 256 + t;
    int v = (i < NN) ? d_cnt[i] : 0;
    sp[t] = v;
    __syncthreads();
    for (int off = 1; off < 256; off <<= 1) {
        int u = 0;
        if (t >= off) u = sp[t - off];
        __syncthreads();
        if (t >= off) sp[t] += u;
        __syncthreads();
    }
    if (i < NN) d_rowptr[i] = d_boff[blockIdx.x] + sp[t] - v;
}

__global__ void k_fill(const int* __restrict__ src, const int* __restrict__ dst) {
    int i = blockIdx.x * blockDim.x + threadIdx.x;
    if (i >= EE / 4) return;
    int4 d = ((const int4*)dst)[i];
    int4 s = ((const int4*)src)[i];
    int p;
    p = atomicAdd(&d_cur[d.x], 1); d_col[d_rowptr[d.x] + p] = s.x;
    p = atomicAdd(&d_cur[d.y], 1); d_col[d_rowptr[d.y] + p] = s.y;
    p = atomicAdd(&d_cur[d.z], 1); d_col[d_rowptr[d.z] + p] = s.z;
    p = atomicAdd(&d_cur[d.w], 1); d_col[d_rowptr[d.w] + p] = s.w;
}

// -------- layer-0 aggregation: fp32 input x, no BN --------
__global__ __launch_bounds__(256) void k_agg_f32(const float* __restrict__ hin,
                                                 const float* __restrict__ eps) {
    int t = blockIdx.x * blockDim.x + threadIdx.x;
    int n = t >> 5;
    int l = t & 31;
    if (n >= NN) return;

    const float4* h4 = (const float4*)hin;
    float s = 1.f + __ldg(&eps[0]);
    float4 v = __ldg(&h4[(size_t)n * 32 + l]);
    float ax = v.x * s, ay = v.y * s, az = v.z * s, aw = v.w * s;

    int p0 = d_rowptr[n], p1 = d_rowptr[n + 1];
    for (int p = p0; p < p1; p += 8) {
        int idx[8];
        float msk[8];
#pragma unroll
        for (int j = 0; j < 8; j++) {
            int pp = p + j;
            msk[j] = (pp < p1) ? 1.f : 0.f;
            idx[j] = __ldg(&d_col[pp < p1 ? pp : (p1 - 1)]);
        }
        float4 u[8];
#pragma unroll
        for (int j = 0; j < 8; j++) u[j] = __ldg(&h4[(size_t)idx[j] * 32 + l]);
#pragma unroll
        for (int j = 0; j < 8; j++) {
            ax = fmaf(msk[j], u[j].x, ax);
            ay = fmaf(msk[j], u[j].y, ay);
            az = fmaf(msk[j], u[j].z, az);
            aw = fmaf(msk[j], u[j].w, aw);
        }
    }
    ((float4*)d_z)[(size_t)n * 32 + l] = make_float4(ax, ay, az, aw);
}

// -------- layers 1+: fp16 input with lazy BN+relu --------
__global__ __launch_bounds__(256) void k_agg_f16(const __half* __restrict__ hin,
                                                 const float* __restrict__ eps, int layer,
                                                 const float* __restrict__ g2,
                                                 const float* __restrict__ bt2,
                                                 const float* __restrict__ statsPrev) {
    int t = blockIdx.x * blockDim.x + threadIdx.x;
    int n = t >> 5;
    int l = t & 31;
    if (n >= NN) return;

    float sc0, sc1, sc2, sc3, sh0, sh1, sh2, sh3;
    {
        int c = l * 4;
        float scs[4], shs[4];
#pragma unroll
        for (int j = 0; j < 4; j++) {
            float s = 0.f, q = 0.f;
#pragma unroll
            for (int sl = 0; sl < STAT_SLICES; sl++) {
                s += __ldg(&statsPrev[sl * 2 * HH + c + j]);
                q += __ldg(&statsPrev[sl * 2 * HH + HH + c + j]);
            }
            float m = s * (1.f / NN);
            float var = q * (1.f / NN) - m * m;
            float rs_ = rsqrtf(var + BN_EPS);
            scs[j] = rs_ * __ldg(&g2[c + j]);
            shs[j] = __ldg(&bt2[c + j]) - m * scs[j];
        }
        sc0 = scs[0]; sc1 = scs[1]; sc2 = scs[2]; sc3 = scs[3];
        sh0 = shs[0]; sh1 = shs[1]; sh2 = shs[2]; sh3 = shs[3];
    }

    const uint2* h2 = (const uint2*)hin;
    auto rd = [&](int node) -> float4 {
        uint2 raw = __ldg(&h2[(size_t)node * 32 + l]);
        __half2 p01 = *(__half2*)&raw.x;
        __half2 p23 = *(__half2*)&raw.y;
        float2 f01 = __half22float2(p01);
        float2 f23 = __half22float2(p23);
        float4 u;
        u.x = fmaxf(fmaf(f01.x, sc0, sh0), 0.f);
        u.y = fmaxf(fmaf(f01.y, sc1, sh1), 0.f);
        u.z = fmaxf(fmaf(f23.x, sc2, sh2), 0.f);
        u.w = fmaxf(fmaf(f23.y, sc3, sh3), 0.f);
        return u;
    };

    float s = 1.f + __ldg(&eps[layer]);
    float4 v = rd(n);
    float ax = v.x * s, ay = v.y * s, az = v.z * s, aw = v.w * s;

    int p0 = d_rowptr[n], p1 = d_rowptr[n + 1];
    for (int p = p0; p < p1; p += 8) {
        int idx[8];
        float msk[8];
#pragma unroll
        for (int j = 0; j < 8; j++) {
            int pp = p + j;
            msk[j] = (pp < p1) ? 1.f : 0.f;
            idx[j] = __ldg(&d_col[pp < p1 ? pp : (p1 - 1)]);
        }
        float4 u[8];
#pragma unroll
        for (int j = 0; j < 8; j++) u[j] = rd(idx[j]);
#pragma unroll
        for (int j = 0; j < 8; j++) {
            ax = fmaf(msk[j], u[j].x, ax);
            ay = fmaf(msk[j], u[j].y, ay);
            az = fmaf(msk[j], u[j].z, az);
            aw = fmaf(msk[j], u[j].w, aw);
        }
    }
    ((float4*)d_z)[(size_t)n * 32 + l] = make_float4(ax, ay, az, aw);
}

// -------- TF32 tensor-core GEMM, BM=64 (782 blocks -> 88% wave efficiency) --------
// smem words: Ws [128][132] = 16896; As [64][36] = 2304; stats 512 -> 19712 words (78.8KB)
#define GEMM_SMEM_WORDS 19712
#define GEMM_SMEM_BYTES (GEMM_SMEM_WORDS * 4)
#define GEMM_BM 64

__device__ __forceinline__ void mma_tf32(float& c0, float& c1, float& c2, float& c3,
                                         uint32_t a0, uint32_t a1, uint32_t a2, uint32_t a3,
                                         uint32_t b0, uint32_t b1) {
    asm volatile(
        "mma.sync.aligned.m16n8k8.row.col.f32.tf32.tf32.f32 "
        "{%0,%1,%2,%3}, {%4,%5,%6,%7}, {%8,%9}, {%0,%1,%2,%3};"
        : "+f"(c0), "+f"(c1), "+f"(c2), "+f"(c3)
        : "r"(a0), "r"(a1), "r"(a2), "r"(a3), "r"(b0), "r"(b1));
}

template <bool BN_IN, bool HALF_OUT>
__global__ __launch_bounds__(256, 2) void k_gemm_tc(
    const float* __restrict__ A, const float* __restrict__ W,
    const float* __restrict__ bias,
    const float* __restrict__ bng, const float* __restrict__ bnb,
    const float* __restrict__ instats,
    void* __restrict__ outv, float* __restrict__ outstats) {

    extern __shared__ uint32_t sm[];
    uint32_t* Ws = sm;                     // [128][132]
    uint32_t* As = sm + 16896;             // [64][36]
    float* ssum = (float*)(sm + 19200);
    float* ssq  = (float*)(sm + 19328);
    float* smu  = (float*)(sm + 19456);
    float* srs  = (float*)(sm + 19584);

    int tid = threadIdx.x;
    int lane = tid & 31;
    int warp = tid >> 5;
    int m0 = (warp >> 2) * 32;             // 2 warps in M
    int n0 = (warp & 3) * 32;              // 4 warps in N
    int row0 = blockIdx.x * GEMM_BM;

    if (tid < HH) { ssum[tid] = 0.f; ssq[tid] = 0.f; }
    if (BN_IN) {
        if (tid < HH) {
            float s = 0.f, q = 0.f;
#pragma unroll
            for (int sl = 0; sl < STAT_SLICES; sl++) {
                s += instats[sl * 2 * HH + tid];
                q += instats[sl * 2 * HH + HH + tid];
            }
            float m = s * (1.f / NN);
            float var = q * (1.f / NN) - m * m;
            smu[tid] = m;
            srs[tid] = rsqrtf(var + BN_EPS);
        }
    }

    // stage W -> smem, raw fp32 bits as tf32 (HW truncates), float4 stores
    const float4* W4 = (const float4*)W;
#pragma unroll
    for (int i = 0; i < 16; i++) {
        int f = tid + i * 256;
        int k = f >> 5, c = f & 31;
        float4 w = W4[k * 32 + c];
        *(float4*)(Ws + k * 132 + c * 4) = w;
    }
    if (BN_IN) __syncthreads();   // smu/srs ready before loadA

    const float4* A4 = (const float4*)A;

    float4 areg[2];
    auto loadA = [&](int kt) {
#pragma unroll
        for (int i = 0; i < 2; i++) {
            int f = tid + i * 256;         // 0..511
            int r = f >> 3, c8 = f & 7;    // r 0..63
            int gcol = kt + c8 * 4;
            float4 v = make_float4(0.f, 0.f, 0.f, 0.f);
            int gr = row0 + r;
            if (gr < NN) v = A4[(size_t)gr * 32 + (kt >> 2) + c8];
            if (BN_IN) {
                v.x = fmaxf((v.x - smu[gcol + 0]) * srs[gcol + 0] * bng[gcol + 0] + bnb[gcol + 0], 0.f);
                v.y = fmaxf((v.y - smu[gcol + 1]) * srs[gcol + 1] * bng[gcol + 1] + bnb[gcol + 1], 0.f);
                v.z = fmaxf((v.z - smu[gcol + 2]) * srs[gcol + 2] * bng[gcol + 2] + bnb[gcol + 2], 0.f);
                v.w = fmaxf((v.w - smu[gcol + 3]) * srs[gcol + 3] * bng[gcol + 3] + bnb[gcol + 3], 0.f);
            }
            areg[i] = v;
        }
    };
    auto storeA = [&]() {
#pragma unroll
        for (int i = 0; i < 2; i++) {
            int f = tid + i * 256;
            int r = f >> 3, c8 = f & 7;
            *(float4*)(As + r * 36 + c8 * 4) = areg[i];
        }
    };

    float acc[2][4][4];
#pragma unroll
    for (int mi = 0; mi < 2; mi++)
#pragma unroll
        for (int ni = 0; ni < 4; ni++)
#pragma unroll
            for (int r = 0; r < 4; r++) acc[mi][ni][r] = 0.f;

    loadA(0);

#pragma unroll
    for (int ch = 0; ch < 4; ch++) {
        if (ch > 0) __syncthreads();
        storeA();
        __syncthreads();
        if (ch < 3) loadA((ch + 1) * 32);

        int ktg = ch * 32;
#pragma unroll
        for (int ks = 0; ks < 4; ks++) {
            int kl = ks * 8 + (lane & 3);
            uint32_t a[2][4];
#pragma unroll
            for (int mi = 0; mi < 2; mi++) {
                int r = m0 + mi * 16 + (lane >> 2);
                a[mi][0] = As[r * 36 + kl];
                a[mi][1] = As[(r + 8) * 36 + kl];
                a[mi][2] = As[r * 36 + kl + 4];
                a[mi][3] = As[(r + 8) * 36 + kl + 4];
            }
            int kg = ktg + ks * 8 + (lane & 3);
            uint32_t b[4][2];
#pragma unroll
            for (int ni = 0; ni < 4; ni++) {
                int nc = n0 + ni * 8 + (lane >> 2);
                b[ni][0] = Ws[kg * 132 + nc];
                b[ni][1] = Ws[(kg + 4) * 132 + nc];
            }
#pragma unroll
            for (int mi = 0; mi < 2; mi++)
#pragma unroll
                for (int ni = 0; ni < 4; ni++)
                    mma_tf32(acc[mi][ni][0], acc[mi][ni][1], acc[mi][ni][2], acc[mi][ni][3],
                             a[mi][0], a[mi][1], a[mi][2], a[mi][3],
                             b[ni][0], b[ni][1]);
        }
    }

    float* outf = (float*)outv;
    __half* outh = (__half*)outv;

    float psum[8], psq[8];
#pragma unroll
    for (int i = 0; i < 8; i++) { psum[i] = 0.f; psq[i] = 0.f; }

#pragma unroll
    for (int ni = 0; ni < 4; ni++) {
        int col = n0 + ni * 8 + 2 * (lane & 3);
        float b0v = bias[col], b1v = bias[col + 1];
#pragma unroll
        for (int mi = 0; mi < 2; mi++) {
            int r = row0 + m0 + mi * 16 + (lane >> 2);
            float v0 = acc[mi][ni][0] + b0v;
            float v1 = acc[mi][ni][1] + b1v;
            float v2 = acc[mi][ni][2] + b0v;
            float v3 = acc[mi][ni][3] + b1v;
            if (r < NN) {
                if (HALF_OUT) *(__half2*)(outh + (size_t)r * HH + col) = __floats2half2_rn(v0, v1);
                else          *(float2*)(outf + (size_t)r * HH + col) = make_float2(v0, v1);
                psum[ni * 2]     += v0;  psq[ni * 2]     += v0 * v0;
                psum[ni * 2 + 1] += v1;  psq[ni * 2 + 1] += v1 * v1;
            }
            if (r + 8 < NN) {
                if (HALF_OUT) *(__half2*)(outh + (size_t)(r + 8) * HH + col) = __floats2half2_rn(v2, v3);
                else          *(float2*)(outf + (size_t)(r + 8) * HH + col) = make_float2(v2, v3);
                psum[ni * 2]     += v2;  psq[ni * 2]     += v2 * v2;
                psum[ni * 2 + 1] += v3;  psq[ni * 2 + 1] += v3 * v3;
            }
        }
    }

#pragma unroll
    for (int mask = 4; mask <= 16; mask <<= 1) {
#pragma unroll
        for (int i = 0; i < 8; i++) {
            psum[i] += __shfl_xor_sync(0xffffffff, psum[i], mask);
            psq[i]  += __shfl_xor_sync(0xffffffff, psq[i], mask);
        }
    }
    if (lane < 4) {
#pragma unroll
        for (int i = 0; i < 8; i++) {
            int col = n0 + 8 * (i >> 1) + 2 * lane + (i & 1);
            atomicAdd(&ssum[col], psum[i]);
            atomicAdd(&ssq[col], psq[i]);
        }
    }
    __syncthreads();
    if (tid < HH) {
        int slice = blockIdx.x & (STAT_SLICES - 1);
        atomicAdd(&outstats[slice * 2 * HH + tid], ssum[tid]);
        atomicAdd(&outstats[slice * 2 * HH + HH + tid], ssq[tid]);
    }
}

// -------- deferred pooling: all layers at once (fp16 h) --------
__global__ void k_pool_all(const float* __restrict__ g2all, const float* __restrict__ bt2all) {
    int g = blockIdx.x;
    int layer = blockIdx.y;
    int c = threadIdx.x;   // 128
    const float* stats = d_stB[layer];
    float s0 = 0.f, q0 = 0.f;
#pragma unroll
    for (int sl = 0; sl < STAT_SLICES; sl++) {
        s0 += stats[sl * 2 * HH + c];
        q0 += stats[sl * 2 * HH + HH + c];
    }
    float m = s0 * (1.f / NN);
    float var = q0 * (1.f / NN) - m * m;
    float rs_ = rsqrtf(var + BN_EPS);
    float sc = rs_ * g2all[layer * HH + c];
    float sh = bt2all[layer * HH + c] - m * sc;
    const __half* h = d_hl[layer];
    int s = d_start[g], e = d_start[g + 1];
    float a0 = 0.f, a1 = 0.f, a2 = 0.f, a3 = 0.f;
    float a4 = 0.f, a5 = 0.f, a6 = 0.f, a7 = 0.f;
    int n = s;
    for (; n + 8 <= e; n += 8) {
        a0 += fmaxf(fmaf(__half2float(h[(size_t)(n + 0) * HH + c]), sc, sh), 0.f);
        a1 += fmaxf(fmaf(__half2float(h[(size_t)(n + 1) * HH + c]), sc, sh), 0.f);
        a2 += fmaxf(fmaf(__half2float(h[(size_t)(n + 2) * HH + c]), sc, sh), 0.f);
        a3 += fmaxf(fmaf(__half2float(h[(size_t)(n + 3) * HH + c]), sc, sh), 0.f);
        a4 += fmaxf(fmaf(__half2float(h[(size_t)(n + 4) * HH + c]), sc, sh), 0.f);
        a5 += fmaxf(fmaf(__half2float(h[(size_t)(n + 5) * HH + c]), sc, sh), 0.f);
        a6 += fmaxf(fmaf(__half2float(h[(size_t)(n + 6) * HH + c]), sc, sh), 0.f);
        a7 += fmaxf(fmaf(__half2float(h[(size_t)(n + 7) * HH + c]), sc, sh), 0.f);
    }
    for (; n < e; ++n) a0 += fmaxf(fmaf(__half2float(h[(size_t)n * HH + c]), sc, sh), 0.f);
    d_pool[(size_t)g * (LL * HH) + layer * HH + c] =
        ((a0 + a1) + (a2 + a3)) + ((a4 + a5) + (a6 + a7));
}

// out[g] = relu(pool[g] @ fc1 + b1) @ fc2 + b2
__global__ void k_head(const float* __restrict__ fc1w, const float* __restrict__ fc1b,
                       const float* __restrict__ fc2w, const float* __restrict__ fc2b,
                       float* __restrict__ out) {
    __shared__ float sp[LL * HH];
    __shared__ float t1[HH];
    int g = blockIdx.x, t = threadIdx.x;   // 128 threads
    for (int k = t; k < LL * HH; k += HH) sp[k] = d_pool[(size_t)g * (LL * HH) + k];
    __syncthreads();
    float acc = fc1b[t];
#pragma unroll 8
    for (int k = 0; k < LL * HH; k++) acc += sp[k] * fc1w[(size_t)k * HH + t];
    t1[t] = fmaxf(acc, 0.f);
    __syncthreads();
    if (t < CC) {
        float a = fc2b[t];
#pragma unroll 8
        for (int j = 0; j < HH; j++) a += t1[j] * fc2w[j * CC + t];
        out[g * CC + t] = a;
    }
}

extern "C" void kernel_launch(void* const* d_in, const int* in_sizes, int n_in,
                              void* d_out, int out_size) {
    const float* x     = (const float*)d_in[0];
    const int*   ei    = (const int*)d_in[1];
    const int*   batch = (const int*)d_in[2];
    const float* W1    = (const float*)d_in[3];
    const float* b1    = (const float*)d_in[4];
    const float* g1    = (const float*)d_in[5];
    const float* bt1   = (const float*)d_in[6];
    const float* W2    = (const float*)d_in[7];
    const float* b2    = (const float*)d_in[8];
    const float* g2    = (const float*)d_in[9];
    const float* bt2   = (const float*)d_in[10];
    const float* eps   = (const float*)d_in[11];
    const float* fc1w  = (const float*)d_in[12];
    const float* fc1b  = (const float*)d_in[13];
    const float* fc2w  = (const float*)d_in[14];
    const float* fc2b  = (const float*)d_in[15];
    float* out = (float*)d_out;

    const int* src = ei;
    const int* dst = ei + EE;

    __half* hl;
    float *zbuf, *ybuf, *stA, *stB;
    cudaGetSymbolAddress((void**)&hl, d_hl);
    cudaGetSymbolAddress((void**)&zbuf, d_z);
    cudaGetSymbolAddress((void**)&ybuf, d_y);
    cudaGetSymbolAddress((void**)&stA, d_stA);
    cudaGetSymbolAddress((void**)&stB, d_stB);

    cudaFuncSetAttribute(k_gemm_tc<false, false>, cudaFuncAttributeMaxDynamicSharedMemorySize, GEMM_SMEM_BYTES);
    cudaFuncSetAttribute(k_gemm_tc<true, true>,   cudaFuncAttributeMaxDynamicSharedMemorySize, GEMM_SMEM_BYTES);

    const int gemm_blocks = (NN + GEMM_BM - 1) / GEMM_BM;   // 782
    const int agg_blocks  = (NN * 32 + 255) / 256;
    const int edge4_blocks = (EE / 4 + 255) / 256;
    const int STL = STAT_SLICES * 2 * HH;

    // ---- per-replay: bounds + zero + CSR build ----
    k_init<<<SCAN_BLOCKS, 256>>>(batch);
    k_hist<<<edge4_blocks, 256>>>(dst);
    k_scan1<<<SCAN_BLOCKS, 256>>>();
    k_scan2<<<1, 256>>>();
    k_scan3<<<SCAN_BLOCKS, 256>>>();
    k_fill<<<edge4_blocks, 256>>>(src, dst);

    for (int i = 0; i < LL; i++) {
        float* stAi = stA + (size_t)i * STL;
        float* stBi = stB + (size_t)i * STL;
        __half* hout = hl + (size_t)i * NN * HH;
        if (i == 0) {
            k_agg_f32<<<agg_blocks, 256>>>(x, eps);
        } else {
            k_agg_f16<<<agg_blocks, 256>>>(hl + (size_t)(i - 1) * NN * HH, eps, i,
                                           g2 + (i - 1) * HH, bt2 + (i - 1) * HH,
                                           stB + (size_t)(i - 1) * STL);
        }
        // y = z @ W1[i] + b1[i]; raw stats -> stA[i]
        k_gemm_tc<false, false><<<gemm_blocks, 256, GEMM_SMEM_BYTES>>>(
            zbuf, W1 + (size_t)i * HH * HH, b1 + i * HH, nullptr, nullptr, nullptr,
            ybuf, stAi);
        // z2 = relu(bn1(y)) @ W2[i] + b2[i]; raw stats -> stB[i]; fp16 out -> d_hl[i]
        k_gemm_tc<true, true><<<gemm_blocks, 256, GEMM_SMEM_BYTES>>>(
            ybuf, W2 + (size_t)i * HH * HH, b2 + i * HH, g1 + i * HH, bt1 + i * HH, stAi,
            hout, stBi);
    }

    dim3 pool_grid(GG, LL);
    k_pool_all<<<pool_grid, HH>>>(g2, bt2);
    k_head<<<GG, HH>>>(fc1w, fc1b, fc2w, fc2b, out);
}

// round 16
// speedup vs baseline: 1.1324x; 1.1324x over previous
#include <cuda_runtime.h>
#include <cuda_bf16.h>
#include <cuda_fp16.h>
#include <cstdint>

#define NN 50000
#define EE 600000
#define HH 128
#define LL 4
#define GG 256
#define CC 10
#define BN_EPS 1e-5f

#define SCAN_BLOCKS ((NN + 255) / 256)   // 196

// -------- device scratch (no allocations allowed) --------
__device__ __half d_hl[LL][NN * HH]; // pre-BN z2 per layer (fp16)
__device__ float d_z[NN * HH];       // agg output (fp32)
__device__ float d_y[NN * HH];       // GEMM1 output (fp32)
__device__ float d_pool[GG * LL * HH];
__device__ float d_stA[LL][2 * HH];  // raw per-layer stats: sum / sumsq
__device__ float d_stB[LL][2 * HH];
__device__ int   d_start[GG + 1];
// CSR (dst-sorted adjacency)
__device__ int   d_cnt[NN];          // zeroed by k_scan_lb for next replay
__device__ int   d_cur[NN];          // zeroed by k_scan_lb for next replay
__device__ int   d_rowptr[NN + 1];
__device__ int   d_col[EE];
__device__ unsigned long long d_scan_state[SCAN_BLOCKS];  // reset by k_fill

// -------- launch 1: graph bounds + histogram + stats zero --------
// invariants on entry: d_cnt == 0, d_cur == 0, d_scan_state == 0
__global__ void k_init_hist(const int* __restrict__ batch, const int* __restrict__ dst) {
    int i = blockIdx.x * blockDim.x + threadIdx.x;
    if (i < EE / 4) {
        int4 d = ((const int4*)dst)[i];
        atomicAdd(&d_cnt[d.x], 1);
        atomicAdd(&d_cnt[d.y], 1);
        atomicAdd(&d_cnt[d.z], 1);
        atomicAdd(&d_cnt[d.w], 1);
    }
    if (i < NN) {
        int g = batch[i];
        if (i == 0) {
            for (int gg = 0; gg <= g; ++gg) d_start[gg] = 0;
        } else {
            int gp = batch[i - 1];
            for (int gg = gp + 1; gg <= g; ++gg) d_start[gg] = i;
        }
        if (i == NN - 1) {
            for (int gg = g + 1; gg <= GG; ++gg) d_start[gg] = NN;
        }
    }
    if (i < LL * 2 * HH) {
        ((float*)d_stA)[i] = 0.f;
        ((float*)d_stB)[i] = 0.f;
    }
}

// -------- launch 2: decoupled-lookback scan; zeroes cnt/cur for next replay --------
__global__ __launch_bounds__(256) void k_scan_lb() {
    __shared__ int sp[256];
    __shared__ int s_excl;
    int t = threadIdx.x, b = blockIdx.x;
    int i = b * 256 + t;
    int v = (i < NN) ? d_cnt[i] : 0;
    sp[t] = v;
    if (i < NN) { d_cnt[i] = 0; d_cur[i] = 0; }
    __syncthreads();
    for (int off = 1; off < 256; off <<= 1) {
        int u = 0;
        if (t >= off) u = sp[t - off];
        __syncthreads();
        if (t >= off) sp[t] += u;
        __syncthreads();
    }
    int total = sp[255];
    if (t == 0) {
        if (b == 0) {
            s_excl = 0;
            atomicExch(&d_scan_state[0], (2ULL << 32) | (unsigned)total);
        } else {
            atomicExch(&d_scan_state[b], (1ULL << 32) | (unsigned)total);
            long long run = 0;
            int p = b - 1;
            while (p >= 0) {
                unsigned long long s;
                do { s = atomicAdd(&d_scan_state[p], 0ULL); } while ((s >> 32) == 0ULL);
                run += (unsigned)(s & 0xffffffffu);
                if ((s >> 32) == 2ULL) break;
                p--;
            }
            s_excl = (int)run;
            atomicExch(&d_scan_state[b], (2ULL << 32) | (unsigned)(run + total));
        }
    }
    __syncthreads();
    if (i < NN) d_rowptr[i] = s_excl + sp[t] - v;
    if (b == SCAN_BLOCKS - 1 && t == 255) d_rowptr[NN] = EE;
}

// -------- launch 3: CSR fill + reset scan state for next replay --------
__global__ void k_fill(const int* __restrict__ src, const int* __restrict__ dst) {
    int i = blockIdx.x * blockDim.x + threadIdx.x;
    if (i < SCAN_BLOCKS) d_scan_state[i] = 0ULL;
    if (i >= EE / 4) return;
    int4 d = ((const int4*)dst)[i];
    int4 s = ((const int4*)src)[i];
    int p;
    p = atomicAdd(&d_cur[d.x], 1); d_col[d_rowptr[d.x] + p] = s.x;
    p = atomicAdd(&d_cur[d.y], 1); d_col[d_rowptr[d.y] + p] = s.y;
    p = atomicAdd(&d_cur[d.z], 1); d_col[d_rowptr[d.z] + p] = s.z;
    p = atomicAdd(&d_cur[d.w], 1); d_col[d_rowptr[d.w] + p] = s.w;
}

// -------- layer-0 aggregation: fp32 input x, no BN --------
__global__ __launch_bounds__(256) void k_agg_f32(const float* __restrict__ hin,
                                                 const float* __restrict__ eps) {
    int t = blockIdx.x * blockDim.x + threadIdx.x;
    int n = t >> 5;
    int l = t & 31;
    if (n >= NN) return;

    const float4* h4 = (const float4*)hin;
    float s = 1.f + __ldg(&eps[0]);
    float4 v = __ldg(&h4[(size_t)n * 32 + l]);
    float ax = v.x * s, ay = v.y * s, az = v.z * s, aw = v.w * s;

    int p0 = d_rowptr[n], p1 = d_rowptr[n + 1];
    for (int p = p0; p < p1; p += 8) {
        int idx[8];
        float msk[8];
#pragma unroll
        for (int j = 0; j < 8; j++) {
            int pp = p + j;
            msk[j] = (pp < p1) ? 1.f : 0.f;
            idx[j] = __ldg(&d_col[pp < p1 ? pp : (p1 - 1)]);
        }
        float4 u[8];
#pragma unroll
        for (int j = 0; j < 8; j++) u[j] = __ldg(&h4[(size_t)idx[j] * 32 + l]);
#pragma unroll
        for (int j = 0; j < 8; j++) {
            ax = fmaf(msk[j], u[j].x, ax);
            ay = fmaf(msk[j], u[j].y, ay);
            az = fmaf(msk[j], u[j].z, az);
            aw = fmaf(msk[j], u[j].w, aw);
        }
    }
    ((float4*)d_z)[(size_t)n * 32 + l] = make_float4(ax, ay, az, aw);
}

// -------- layers 1+: fp16 input with lazy BN+relu --------
__global__ __launch_bounds__(256) void k_agg_f16(const __half* __restrict__ hin,
                                                 const float* __restrict__ eps, int layer,
                                                 const float* __restrict__ g2,
                                                 const float* __restrict__ bt2,
                                                 const float* __restrict__ statsPrev) {
    int t = blockIdx.x * blockDim.x + threadIdx.x;
    int n = t >> 5;
    int l = t & 31;
    if (n >= NN) return;

    float sc0, sc1, sc2, sc3, sh0, sh1, sh2, sh3;
    {
        int c = l * 4;
        float scs[4], shs[4];
#pragma unroll
        for (int j = 0; j < 4; j++) {
            float s = __ldg(&statsPrev[c + j]);
            float q = __ldg(&statsPrev[HH + c + j]);
            float m = s * (1.f / NN);
            float var = q * (1.f / NN) - m * m;
            float rs_ = rsqrtf(var + BN_EPS);
            scs[j] = rs_ * __ldg(&g2[c + j]);
            shs[j] = __ldg(&bt2[c + j]) - m * scs[j];
        }
        sc0 = scs[0]; sc1 = scs[1]; sc2 = scs[2]; sc3 = scs[3];
        sh0 = shs[0]; sh1 = shs[1]; sh2 = shs[2]; sh3 = shs[3];
    }

    const uint2* h2 = (const uint2*)hin;
    auto rd = [&](int node) -> float4 {
        uint2 raw = __ldg(&h2[(size_t)node * 32 + l]);
        __half2 p01 = *(__half2*)&raw.x;
        __half2 p23 = *(__half2*)&raw.y;
        float2 f01 = __half22float2(p01);
        float2 f23 = __half22float2(p23);
        float4 u;
        u.x = fmaxf(fmaf(f01.x, sc0, sh0), 0.f);
        u.y = fmaxf(fmaf(f01.y, sc1, sh1), 0.f);
        u.z = fmaxf(fmaf(f23.x, sc2, sh2), 0.f);
        u.w = fmaxf(fmaf(f23.y, sc3, sh3), 0.f);
        return u;
    };

    float s = 1.f + __ldg(&eps[layer]);
    float4 v = rd(n);
    float ax = v.x * s, ay = v.y * s, az = v.z * s, aw = v.w * s;

    int p0 = d_rowptr[n], p1 = d_rowptr[n + 1];
    for (int p = p0; p < p1; p += 8) {
        int idx[8];
        float msk[8];
#pragma unroll
        for (int j = 0; j < 8; j++) {
            int pp = p + j;
            msk[j] = (pp < p1) ? 1.f : 0.f;
            idx[j] = __ldg(&d_col[pp < p1 ? pp : (p1 - 1)]);
        }
        float4 u[8];
#pragma unroll
        for (int j = 0; j < 8; j++) u[j] = rd(idx[j]);
#pragma unroll
        for (int j = 0; j < 8; j++) {
            ax = fmaf(msk[j], u[j].x, ax);
            ay = fmaf(msk[j], u[j].y, ay);
            az = fmaf(msk[j], u[j].z, az);
            aw = fmaf(msk[j], u[j].w, aw);
        }
    }
    ((float4*)d_z)[(size_t)n * 32 + l] = make_float4(ax, ay, az, aw);
}

// -------- TF32 tensor-core GEMM: persistent blocks, BM=128, W staged once --------
// smem words: Ws [128][132] = 16896; As [128][36] = 4608; stats 512 -> 22016 words (88KB)
#define GEMM_SMEM_WORDS 22016
#define GEMM_SMEM_BYTES (GEMM_SMEM_WORDS * 4)
#define GEMM_NTILES ((NN + 127) / 128)   // 391
#define GEMM_GRID 296                    // 2 CTAs/SM * 148 SMs

__device__ __forceinline__ void mma_tf32(float& c0, float& c1, float& c2, float& c3,
                                         uint32_t a0, uint32_t a1, uint32_t a2, uint32_t a3,
                                         uint32_t b0, uint32_t b1) {
    asm volatile(
        "mma.sync.aligned.m16n8k8.row.col.f32.tf32.tf32.f32 "
        "{%0,%1,%2,%3}, {%4,%5,%6,%7}, {%8,%9}, {%0,%1,%2,%3};"
        : "+f"(c0), "+f"(c1), "+f"(c2), "+f"(c3)
        : "r"(a0), "r"(a1), "r"(a2), "r"(a3), "r"(b0), "r"(b1));
}

template <bool BN_IN, bool HALF_OUT>
__global__ __launch_bounds__(256, 2) void k_gemm_tc(
    const float* __restrict__ A, const float* __restrict__ W,
    const float* __restrict__ bias,
    const float* __restrict__ bng, const float* __restrict__ bnb,
    const float* __restrict__ instats,
    void* __restrict__ outv, float* __restrict__ outstats) {

    extern __shared__ uint32_t sm[];
    uint32_t* Ws = sm;                     // [128][132]
    uint32_t* As = sm + 16896;             // [128][36]
    float* ssum = (float*)(sm + 21504);
    float* ssq  = (float*)(sm + 21632);
    float* smu  = (float*)(sm + 21760);
    float* srs  = (float*)(sm + 21888);

    int tid = threadIdx.x;
    int lane = tid & 31;
    int warp = tid >> 5;
    int m0 = (warp >> 1) * 32;
    int n0 = (warp & 1) * 64;

    if (tid < HH) { ssum[tid] = 0.f; ssq[tid] = 0.f; }
    if (BN_IN) {
        if (tid < HH) {
            float s = instats[tid], q = instats[HH + tid];
            float m = s * (1.f / NN);
            float var = q * (1.f / NN) - m * m;
            smu[tid] = m;
            srs[tid] = rsqrtf(var + BN_EPS);
        }
    }

    // stage W once per block: raw fp32 bits as tf32 (HW truncates), float4 stores
    const float4* W4 = (const float4*)W;
#pragma unroll
    for (int i = 0; i < 16; i++) {
        int f = tid + i * 256;
        int k = f >> 5, c = f & 31;
        float4 w = W4[k * 32 + c];
        *(float4*)(Ws + k * 132 + c * 4) = w;
    }
    __syncthreads();   // Ws + (BN_IN) smu/srs visible

    const float4* A4 = (const float4*)A;
    float* outf = (float*)outv;
    __half* outh = (__half*)outv;

    float4 areg[4];
    int a_r = tid >> 3, a_c8 = tid & 7;    // fixed per-thread A slot

    for (int tile = blockIdx.x; tile < GEMM_NTILES; tile += GEMM_GRID) {
        int row0 = tile * 128;

        auto loadA = [&](int kt) {
#pragma unroll
            for (int i = 0; i < 4; i++) {
                int r = a_r + i * 32;
                int gcol = kt + a_c8 * 4;
                float4 v = make_float4(0.f, 0.f, 0.f, 0.f);
                int gr = row0 + r;
                if (gr < NN) v = A4[(size_t)gr * 32 + (kt >> 2) + a_c8];
                if (BN_IN) {
                    v.x = fmaxf((v.x - smu[gcol + 0]) * srs[gcol + 0] * bng[gcol + 0] + bnb[gcol + 0], 0.f);
                    v.y = fmaxf((v.y - smu[gcol + 1]) * srs[gcol + 1] * bng[gcol + 1] + bnb[gcol + 1], 0.f);
                    v.z = fmaxf((v.z - smu[gcol + 2]) * srs[gcol + 2] * bng[gcol + 2] + bnb[gcol + 2], 0.f);
                    v.w = fmaxf((v.w - smu[gcol + 3]) * srs[gcol + 3] * bng[gcol + 3] + bnb[gcol + 3], 0.f);
                }
                areg[i] = v;
            }
        };
        auto storeA = [&]() {
#pragma unroll
            for (int i = 0; i < 4; i++) {
                int r = a_r + i * 32;
                *(float4*)(As + r * 36 + a_c8 * 4) = areg[i];
            }
        };

        float acc[2][8][4];
#pragma unroll
        for (int mi = 0; mi < 2; mi++)
#pragma unroll
            for (int ni = 0; ni < 8; ni++)
#pragma unroll
                for (int r = 0; r < 4; r++) acc[mi][ni][r] = 0.f;

        loadA(0);

#pragma unroll
        for (int ch = 0; ch < 4; ch++) {
            __syncthreads();               // prior mma (prev chunk/tile) done with As
            storeA();
            __syncthreads();               // As visible
            if (ch < 3) loadA((ch + 1) * 32);

            int ktg = ch * 32;
#pragma unroll
            for (int ks = 0; ks < 4; ks++) {
                int kl = ks * 8 + (lane & 3);
                uint32_t a[2][4];
#pragma unroll
                for (int mi = 0; mi < 2; mi++) {
                    int r = m0 + mi * 16 + (lane >> 2);
                    a[mi][0] = As[r * 36 + kl];
                    a[mi][1] = As[(r + 8) * 36 + kl];
                    a[mi][2] = As[r * 36 + kl + 4];
                    a[mi][3] = As[(r + 8) * 36 + kl + 4];
                }
                int kg = ktg + ks * 8 + (lane & 3);
                uint32_t b[8][2];
#pragma unroll
                for (int ni = 0; ni < 8; ni++) {
                    int nc = n0 + ni * 8 + (lane >> 2);
                    b[ni][0] = Ws[kg * 132 + nc];
                    b[ni][1] = Ws[(kg + 4) * 132 + nc];
                }
#pragma unroll
                for (int mi = 0; mi < 2; mi++)
#pragma unroll
                    for (int ni = 0; ni < 8; ni++)
                        mma_tf32(acc[mi][ni][0], acc[mi][ni][1], acc[mi][ni][2], acc[mi][ni][3],
                                 a[mi][0], a[mi][1], a[mi][2], a[mi][3],
                                 b[ni][0], b[ni][1]);
            }
        }

        // per-tile epilogue: bias + store + per-channel partial stats
        float psum[16], psq[16];
#pragma unroll
        for (int i = 0; i < 16; i++) { psum[i] = 0.f; psq[i] = 0.f; }

#pragma unroll
        for (int ni = 0; ni < 8; ni++) {
            int col = n0 + ni * 8 + 2 * (lane & 3);
            float b0v = bias[col], b1v = bias[col + 1];
#pragma unroll
            for (int mi = 0; mi < 2; mi++) {
                int r = row0 + m0 + mi * 16 + (lane >> 2);
                float v0 = acc[mi][ni][0] + b0v;
                float v1 = acc[mi][ni][1] + b1v;
                float v2 = acc[mi][ni][2] + b0v;
                float v3 = acc[mi][ni][3] + b1v;
                if (r < NN) {
                    if (HALF_OUT) *(__half2*)(outh + (size_t)r * HH + col) = __floats2half2_rn(v0, v1);
                    else          *(float2*)(outf + (size_t)r * HH + col) = make_float2(v0, v1);
                    psum[ni * 2]     += v0;  psq[ni * 2]     += v0 * v0;
                    psum[ni * 2 + 1] += v1;  psq[ni * 2 + 1] += v1 * v1;
                }
                if (r + 8 < NN) {
                    if (HALF_OUT) *(__half2*)(outh + (size_t)(r + 8) * HH + col) = __floats2half2_rn(v2, v3);
                    else          *(float2*)(outf + (size_t)(r + 8) * HH + col) = make_float2(v2, v3);
                    psum[ni * 2]     += v2;  psq[ni * 2]     += v2 * v2;
                    psum[ni * 2 + 1] += v3;  psq[ni * 2 + 1] += v3 * v3;
                }
            }
        }

#pragma unroll
        for (int mask = 4; mask <= 16; mask <<= 1) {
#pragma unroll
            for (int i = 0; i < 16; i++) {
                psum[i] += __shfl_xor_sync(0xffffffff, psum[i], mask);
                psq[i]  += __shfl_xor_sync(0xffffffff, psq[i], mask);
            }
        }
        if (lane < 4) {
#pragma unroll
            for (int i = 0; i < 16; i++) {
                int col = n0 + 8 * (i >> 1) + 2 * lane + (i & 1);
                atomicAdd(&ssum[col], psum[i]);
                atomicAdd(&ssq[col], psq[i]);
            }
        }
    }

    // one global stats flush per block
    __syncthreads();
    if (tid < HH) {
        atomicAdd(&outstats[tid], ssum[tid]);
        atomicAdd(&outstats[HH + tid], ssq[tid]);
    }
}

// -------- deferred pooling: all layers at once (fp16 h) --------
__global__ void k_pool_all(const float* __restrict__ g2all, const float* __restrict__ bt2all) {
    int g = blockIdx.x;
    int layer = blockIdx.y;
    int c = threadIdx.x;   // 128
    const float* stats = d_stB[layer];
    float s0 = stats[c], q0 = stats[HH + c];
    float m = s0 * (1.f / NN);
    float var = q0 * (1.f / NN) - m * m;
    float rs_ = rsqrtf(var + BN_EPS);
    float sc = rs_ * g2all[layer * HH + c];
    float sh = bt2all[layer * HH + c] - m * sc;
    const __half* h = d_hl[layer];
    int s = d_start[g], e = d_start[g + 1];
    float a0 = 0.f, a1 = 0.f, a2 = 0.f, a3 = 0.f;
    float a4 = 0.f, a5 = 0.f, a6 = 0.f, a7 = 0.f;
    int n = s;
    for (; n + 8 <= e; n += 8) {
        a0 += fmaxf(fmaf(__half2float(h[(size_t)(n + 0) * HH + c]), sc, sh), 0.f);
        a1 += fmaxf(fmaf(__half2float(h[(size_t)(n + 1) * HH + c]), sc, sh), 0.f);
        a2 += fmaxf(fmaf(__half2float(h[(size_t)(n + 2) * HH + c]), sc, sh), 0.f);
        a3 += fmaxf(fmaf(__half2float(h[(size_t)(n + 3) * HH + c]), sc, sh), 0.f);
        a4 += fmaxf(fmaf(__half2float(h[(size_t)(n + 4) * HH + c]), sc, sh), 0.f);
        a5 += fmaxf(fmaf(__half2float(h[(size_t)(n + 5) * HH + c]), sc, sh), 0.f);
        a6 += fmaxf(fmaf(__half2float(h[(size_t)(n + 6) * HH + c]), sc, sh), 0.f);
        a7 += fmaxf(fmaf(__half2float(h[(size_t)(n + 7) * HH + c]), sc, sh), 0.f);
    }
    for (; n < e; ++n) a0 += fmaxf(fmaf(__half2float(h[(size_t)n * HH + c]), sc, sh), 0.f);
    d_pool[(size_t)g * (LL * HH) + layer * HH + c] =
        ((a0 + a1) + (a2 + a3)) + ((a4 + a5) + (a6 + a7));
}

// out[g] = relu(pool[g] @ fc1 + b1) @ fc2 + b2
__global__ void k_head(const float* __restrict__ fc1w, const float* __restrict__ fc1b,
                       const float* __restrict__ fc2w, const float* __restrict__ fc2b,
                       float* __restrict__ out) {
    __shared__ float sp[LL * HH];
    __shared__ float t1[HH];
    int g = blockIdx.x, t = threadIdx.x;   // 128 threads
    for (int k = t; k < LL * HH; k += HH) sp[k] = d_pool[(size_t)g * (LL * HH) + k];
    __syncthreads();
    float acc = fc1b[t];
#pragma unroll 8
    for (int k = 0; k < LL * HH; k++) acc += sp[k] * fc1w[(size_t)k * HH + t];
    t1[t] = fmaxf(acc, 0.f);
    __syncthreads();
    if (t < CC) {
        float a = fc2b[t];
#pragma unroll 8
        for (int j = 0; j < HH; j++) a += t1[j] * fc2w[j * CC + t];
        out[g * CC + t] = a;
    }
}

extern "C" void kernel_launch(void* const* d_in, const int* in_sizes, int n_in,
                              void* d_out, int out_size) {
    const float* x     = (const float*)d_in[0];
    const int*   ei    = (const int*)d_in[1];
    const int*   batch = (const int*)d_in[2];
    const float* W1    = (const float*)d_in[3];
    const float* b1    = (const float*)d_in[4];
    const float* g1    = (const float*)d_in[5];
    const float* bt1   = (const float*)d_in[6];
    const float* W2    = (const float*)d_in[7];
    const float* b2    = (const float*)d_in[8];
    const float* g2    = (const float*)d_in[9];
    const float* bt2   = (const float*)d_in[10];
    const float* eps   = (const float*)d_in[11];
    const float* fc1w  = (const float*)d_in[12];
    const float* fc1b  = (const float*)d_in[13];
    const float* fc2w  = (const float*)d_in[14];
    const float* fc2b  = (const float*)d_in[15];
    float* out = (float*)d_out;

    const int* src = ei;
    const int* dst = ei + EE;

    __half* hl;
    float *zbuf, *ybuf, *stA, *stB;
    cudaGetSymbolAddress((void**)&hl, d_hl);
    cudaGetSymbolAddress((void**)&zbuf, d_z);
    cudaGetSymbolAddress((void**)&ybuf, d_y);
    cudaGetSymbolAddress((void**)&stA, d_stA);
    cudaGetSymbolAddress((void**)&stB, d_stB);

    cudaFuncSetAttribute(k_gemm_tc<false, false>, cudaFuncAttributeMaxDynamicSharedMemorySize, GEMM_SMEM_BYTES);
    cudaFuncSetAttribute(k_gemm_tc<true, true>,   cudaFuncAttributeMaxDynamicSharedMemorySize, GEMM_SMEM_BYTES);

    const int agg_blocks  = (NN * 32 + 255) / 256;
    const int big_blocks  = (EE / 4 + 255) / 256;   // covers EE/4 = 150000 > NN

    // ---- per-replay CSR build: 3 launches ----
    k_init_hist<<<big_blocks, 256>>>(batch, dst);
    k_scan_lb<<<SCAN_BLOCKS, 256>>>();
    k_fill<<<big_blocks, 256>>>(src, dst);

    for (int i = 0; i < LL; i++) {
        float* stAi = stA + (size_t)i * 2 * HH;
        float* stBi = stB + (size_t)i * 2 * HH;
        __half* hout = hl + (size_t)i * NN * HH;
        if (i == 0) {
            k_agg_f32<<<agg_blocks, 256>>>(x, eps);
        } else {
            k_agg_f16<<<agg_blocks, 256>>>(hl + (size_t)(i - 1) * NN * HH, eps, i,
                                           g2 + (i - 1) * HH, bt2 + (i - 1) * HH,
                                           stB + (size_t)(i - 1) * 2 * HH);
        }
        // y = z @ W1[i] + b1[i]; raw stats -> stA[i]
        k_gemm_tc<false, false><<<GEMM_GRID, 256, GEMM_SMEM_BYTES>>>(
            zbuf, W1 + (size_t)i * HH * HH, b1 + i * HH, nullptr, nullptr, nullptr,
            ybuf, stAi);
        // z2 = relu(bn1(y)) @ W2[i] + b2[i]; raw stats -> stB[i]; fp16 out -> d_hl[i]
        k_gemm_tc<true, true><<<GEMM_GRID, 256, GEMM_SMEM_BYTES>>>(
            ybuf, W2 + (size_t)i * HH * HH, b2 + i * HH, g1 + i * HH, bt1 + i * HH, stAi,
            hout, stBi);
    }

    dim3 pool_grid(GG, LL);
    k_pool_all<<<pool_grid, HH>>>(g2, bt2);
    k_head<<<GG, HH>>>(fc1w, fc1b, fc2w, fc2b, out);
}